// round 7
// baseline (speedup 1.0000x reference)
#include <cuda_runtime.h>
#include <math.h>
#include <stdint.h>

#define B_   1024
#define D_   2048
#define U_   4096
#define BR_  4
#define HID_ 32
#define K_   (D_ * BR_)   // 8192

#define BM 128
#define BN 256
#define BK 16
#define NITER (K_ / BK)   // 512
#define ROWB  80          // 16 floats (64B) + 16B pad: conflict-free LDSM
#define ASZ   (BM * ROWB)             // 10240
#define BSZ   (BN * ROWB)             // 20480
#define STAGE (ASZ + BSZ)             // 30720
#define NSTAGE 3
#define SMEM_GEMM (STAGE * NSTAGE)    // 92160

// ---------------- device scratch (static, allocation-free) ----------------
__device__ float g_gate[B_ * BR_];      // softmax gating [B,4]
__device__ float g_hid[HID_];           // MLP hidden [32]
__device__ float g_cm[U_];              // connectivity * mask [U]
__device__ float g_xt[B_ * K_];         // A: [B, K] K-major, tf32-rounded
__device__ float g_wt[(size_t)U_ * K_]; // B: [U, K] K-major, tf32-rounded

// ---------------- helpers ----------------
__device__ __forceinline__ float tf32_rna(float x) {
    float r; asm("cvt.rna.tf32.f32 %0, %1;" : "=f"(r) : "f"(x)); return r;
}
__device__ __forceinline__ uint32_t smem_u32(const void* p) {
    uint32_t a;
    asm("{ .reg .u64 t; cvta.to.shared.u64 t, %1; cvt.u32.u64 %0, t; }" : "=r"(a) : "l"(p));
    return a;
}
__device__ __forceinline__ void cp_async16(uint32_t dst, const void* src) {
    asm volatile("cp.async.cg.shared.global [%0], [%1], 16;\n" :: "r"(dst), "l"(src));
}
template <int N> __device__ __forceinline__ void cp_wait() {
    asm volatile("cp.async.wait_group %0;\n" :: "n"(N) : "memory");
}
__device__ __forceinline__ void ldsm_x4(uint32_t& r0, uint32_t& r1, uint32_t& r2,
                                        uint32_t& r3, uint32_t addr) {
    asm volatile("ldmatrix.sync.aligned.m8n8.x4.shared.b16 {%0,%1,%2,%3}, [%4];"
                 : "=r"(r0), "=r"(r1), "=r"(r2), "=r"(r3) : "r"(addr));
}
__device__ __forceinline__ void mma_tf32(float& c0, float& c1, float& c2, float& c3,
                                         uint32_t a0, uint32_t a1, uint32_t a2, uint32_t a3,
                                         uint32_t b0, uint32_t b1) {
    asm volatile(
        "mma.sync.aligned.m16n8k8.row.col.f32.tf32.tf32.f32 "
        "{%0,%1,%2,%3}, {%4,%5,%6,%7}, {%8,%9}, {%0,%1,%2,%3};\n"
        : "+f"(c0), "+f"(c1), "+f"(c2), "+f"(c3)
        : "r"(a0), "r"(a1), "r"(a2), "r"(a3), "r"(b0), "r"(b1));
}

// ---------------- K1: gating = softmax(x @ Wg + bg) over 4 branches -------
__global__ void gating_kernel(const float* __restrict__ x,
                              const float* __restrict__ Wg,
                              const float* __restrict__ bg) {
    int b = blockIdx.x, tid = threadIdx.x;
    const float* xr = x + b * D_;
    float p0 = 0.f, p1 = 0.f, p2 = 0.f, p3 = 0.f;
    for (int d = tid; d < D_; d += 256) {
        float xv = xr[d];
        float4 wv = *(const float4*)(Wg + d * 4);
        p0 += xv * wv.x; p1 += xv * wv.y; p2 += xv * wv.z; p3 += xv * wv.w;
    }
    __shared__ float s[256][4];
    s[tid][0] = p0; s[tid][1] = p1; s[tid][2] = p2; s[tid][3] = p3;
    __syncthreads();
    for (int off = 128; off > 0; off >>= 1) {
        if (tid < off) {
            #pragma unroll
            for (int k = 0; k < 4; k++) s[tid][k] += s[tid + off][k];
        }
        __syncthreads();
    }
    if (tid == 0) {
        float l[4], m = -1e30f;
        #pragma unroll
        for (int k = 0; k < 4; k++) { l[k] = s[0][k] + bg[k]; m = fmaxf(m, l[k]); }
        float e[4], sum = 0.f;
        #pragma unroll
        for (int k = 0; k < 4; k++) { e[k] = expf(l[k] - m); sum += e[k]; }
        float inv = 1.f / sum;
        #pragma unroll
        for (int k = 0; k < 4; k++) g_gate[b * 4 + k] = e[k] * inv;
    }
}

// ---------------- K2: h = relu(avg @ W1 + b1), [32] ----------------------
__global__ void hidden_kernel(const float* __restrict__ avg,
                              const float* __restrict__ W1,
                              const float* __restrict__ b1) {
    int tid = threadIdx.x;
    int j = tid & 31, grp = tid >> 5;
    float p = 0.f;
    for (int u = grp; u < U_; u += 8)
        p += avg[u] * W1[u * HID_ + j];
    __shared__ float s[8][32];
    s[grp][j] = p;
    __syncthreads();
    if (grp == 0) {
        float sum = 0.f;
        #pragma unroll
        for (int g = 0; g < 8; g++) sum += s[g][j];
        g_hid[j] = fmaxf(sum + b1[j], 0.f);
    }
}

// ---------------- K3: cm = sigmoid(h @ W2 + b2) * mask, [U] --------------
__global__ void conn_kernel(const float* __restrict__ W2,
                            const float* __restrict__ b2,
                            const float* __restrict__ mask) {
    __shared__ float h[HID_];
    int tid = threadIdx.x;
    if (tid < HID_) h[tid] = g_hid[tid];
    __syncthreads();
    int u = blockIdx.x * 256 + tid;
    float acc = b2[u];
    #pragma unroll
    for (int j = 0; j < HID_; j++) acc += h[j] * W2[j * U_ + u];
    g_cm[u] = mask[u] / (1.f + expf(-acc));
}

// ---------------- K4: x~[b, 4d+k] = tf32(x[b,d] * g[b,k]) ----------------
__global__ void xt_kernel(const float* __restrict__ x) {
    int idx = blockIdx.x * 256 + threadIdx.x;   // over B*D
    int b = idx >> 11;
    float xv = x[idx];
    float4 gv = *(const float4*)(g_gate + b * 4);
    float4 o;
    o.x = tf32_rna(xv * gv.x); o.y = tf32_rna(xv * gv.y);
    o.z = tf32_rna(xv * gv.z); o.w = tf32_rna(xv * gv.w);
    *(float4*)(g_xt + (size_t)idx * 4) = o;
}

// ------- K5: W~[u][4d+k] = tf32(w[d,u,k]*sigmoid(delay)), smem transpose --
// block: 16 d x 32 u tile; skips blocks whose entire u-range is masked
// (stale/zero g_wt there is multiplied by cm==0 in the GEMM epilogue).
__global__ void wt_kernel(const float* __restrict__ w,
                          const float* __restrict__ delay) {
    int d0 = blockIdx.x * 16, u0 = blockIdx.y * 32;
    int tid = threadIdx.x;
    float cmv = g_cm[u0 + (tid & 31)];
    if (!__syncthreads_or(cmv != 0.f)) return;

    __shared__ float s[16][132];
    #pragma unroll
    for (int i = 0; i < 8; i++) {
        int idx = i * 256 + tid;
        int dl = idx >> 7, c = idx & 127;          // c = u_l*4 + k
        size_t g = (size_t)(d0 + dl) * (U_ * BR_) + (size_t)u0 * 4 + c;
        float wv = w[g], dv = delay[g];
        s[dl][c] = tf32_rna(wv / (1.f + __expf(-dv)));
    }
    __syncthreads();
    #pragma unroll
    for (int i = 0; i < 8; i++) {
        int idx = i * 256 + tid;
        int ul = idx >> 6, q = idx & 63;           // q = d_l*4 + k
        g_wt[(size_t)(u0 + ul) * K_ + d0 * 4 + q] = s[q >> 2][ul * 4 + (q & 3)];
    }
}

// ---------------- K6: tf32 mma.sync GEMM, ldmatrix operand path ----------
__device__ __forceinline__ void load_stage(uint32_t stagebase, int chunk,
                                           int bm, int bn, int tid) {
    // A: 128 rows x 64B (4 chunks of 16B)
    #pragma unroll
    for (int i = 0; i < 2; i++) {
        int id = i * 256 + tid;
        int row = id >> 2, c = id & 3;
        cp_async16(stagebase + row * ROWB + c * 16,
                   g_xt + (size_t)(bm * BM + row) * K_ + chunk * BK + c * 4);
    }
    // B: 256 rows x 64B
    #pragma unroll
    for (int i = 0; i < 4; i++) {
        int id = i * 256 + tid;
        int row = id >> 2, c = id & 3;
        cp_async16(stagebase + ASZ + row * ROWB + c * 16,
                   g_wt + (size_t)(bn * BN + row) * K_ + chunk * BK + c * 4);
    }
    asm volatile("cp.async.commit_group;\n" ::: "memory");
}

__global__ __launch_bounds__(256, 1)
void gemm_tf32_kernel(const float* __restrict__ bias, float* __restrict__ out) {
    extern __shared__ char smem[];
    const uint32_t sb = smem_u32(smem);
    const int tid = threadIdx.x, wid = tid >> 5, lane = tid & 31;
    const int bm = blockIdx.x, bn = blockIdx.y;

    // --- data-driven tile skip over 256-wide N tile ---
    float cmv = g_cm[bn * BN + tid];
    if (!__syncthreads_or(cmv != 0.f)) {
        int row = bm * BM + (tid >> 1);
        float* op = out + (size_t)row * U_ + bn * BN + (tid & 1) * 128;
        float4 z = make_float4(0.f, 0.f, 0.f, 0.f);
        #pragma unroll
        for (int j = 0; j < 32; j++) *(float4*)(op + j * 4) = z;
        return;
    }

    const int wm = (wid >> 2) * 64;       // warp M offset (2 warp-rows)
    const int wn = (wid & 3) * 64;        // warp N offset (4 warp-cols)
    const int r8 = lane & 7;
    const int half = (lane >> 3) & 1;
    const int kh = lane >> 4;
    // ldmatrix lane-address bases (per-matrix row pointers)
    const uint32_t aoff = (uint32_t)((wm + half * 8 + r8) * ROWB + kh * 16);
    const uint32_t boff = (uint32_t)(ASZ + (wn + half * 8 + r8) * ROWB + kh * 16);

    float acc[4][8][4];
    #pragma unroll
    for (int i = 0; i < 4; i++)
        #pragma unroll
        for (int j = 0; j < 8; j++)
            #pragma unroll
            for (int r = 0; r < 4; r++) acc[i][j][r] = 0.f;

    // prologue: stages 0,1
    load_stage(sb, 0, bm, bn, tid);
    load_stage(sb + STAGE, 1, bm, bn, tid);

    uint32_t stage = 0;                    // byte offset of current stage
    for (int t = 0; t < NITER; t++) {
        if (t + 2 < NITER) {
            uint32_t nstage = stage + 2 * STAGE;
            if (nstage >= NSTAGE * STAGE) nstage -= NSTAGE * STAGE;
            load_stage(sb + nstage, t + 2, bm, bn, tid);
            cp_wait<2>();
        } else if (t + 1 < NITER) {
            cp_wait<1>();
        } else {
            cp_wait<0>();
        }
        __syncthreads();

        const uint32_t abase = sb + stage + aoff;
        const uint32_t bbase = sb + stage + boff;
        #pragma unroll
        for (int ks = 0; ks < 2; ks++) {
            uint32_t a[4][4], b[4][4];
            #pragma unroll
            for (int mi = 0; mi < 4; mi++)
                ldsm_x4(a[mi][0], a[mi][1], a[mi][2], a[mi][3],
                        abase + mi * (16 * ROWB) + ks * 32);
            #pragma unroll
            for (int nn = 0; nn < 4; nn++)
                ldsm_x4(b[nn][0], b[nn][1], b[nn][2], b[nn][3],
                        bbase + nn * (16 * ROWB) + ks * 32);
            #pragma unroll
            for (int mi = 0; mi < 4; mi++)
                #pragma unroll
                for (int nn = 0; nn < 4; nn++) {
                    mma_tf32(acc[mi][2*nn][0], acc[mi][2*nn][1],
                             acc[mi][2*nn][2], acc[mi][2*nn][3],
                             a[mi][0], a[mi][1], a[mi][2], a[mi][3],
                             b[nn][0], b[nn][2]);
                    mma_tf32(acc[mi][2*nn+1][0], acc[mi][2*nn+1][1],
                             acc[mi][2*nn+1][2], acc[mi][2*nn+1][3],
                             a[mi][0], a[mi][1], a[mi][2], a[mi][3],
                             b[nn][1], b[nn][3]);
                }
        }
        __syncthreads();
        stage += STAGE;
        if (stage >= NSTAGE * STAGE) stage = 0;
    }

    // --- epilogue: + sum_k gate[b,k]*bias[u,k], * cm[u], relu ---
    const int g = lane >> 2, tig = lane & 3;
    #pragma unroll
    for (int mi = 0; mi < 4; mi++) {
        int r0 = bm * BM + wm + mi * 16 + g;
        int r1 = r0 + 8;
        float4 g0 = *(const float4*)(g_gate + r0 * 4);
        float4 g1 = *(const float4*)(g_gate + r1 * 4);
        #pragma unroll
        for (int ni = 0; ni < 8; ni++) {
            int u0 = bn * BN + wn + ni * 8 + 2 * tig;
            float cm0 = g_cm[u0], cm1 = g_cm[u0 + 1];
            float4 bs0 = *(const float4*)(bias + (size_t)u0 * 4);
            float4 bs1 = *(const float4*)(bias + (size_t)(u0 + 1) * 4);
            float v0 = acc[mi][ni][0] + g0.x * bs0.x + g0.y * bs0.y + g0.z * bs0.z + g0.w * bs0.w;
            float v1 = acc[mi][ni][1] + g0.x * bs1.x + g0.y * bs1.y + g0.z * bs1.z + g0.w * bs1.w;
            float v2 = acc[mi][ni][2] + g1.x * bs0.x + g1.y * bs0.y + g1.z * bs0.z + g1.w * bs0.w;
            float v3 = acc[mi][ni][3] + g1.x * bs1.x + g1.y * bs1.y + g1.z * bs1.z + g1.w * bs1.w;
            *(float2*)(out + (size_t)r0 * U_ + u0) =
                make_float2(fmaxf(v0 * cm0, 0.f), fmaxf(v1 * cm1, 0.f));
            *(float2*)(out + (size_t)r1 * U_ + u0) =
                make_float2(fmaxf(v2 * cm0, 0.f), fmaxf(v3 * cm1, 0.f));
        }
    }
}

// ---------------- launch ----------------
extern "C" void kernel_launch(void* const* d_in, const int* in_sizes, int n_in,
                              void* d_out, int out_size) {
    const float* inputs = (const float*)d_in[0];
    const float* w      = (const float*)d_in[1];
    const float* bias   = (const float*)d_in[2];
    const float* delay  = (const float*)d_in[3];
    const float* Wg     = (const float*)d_in[4];
    const float* bg     = (const float*)d_in[5];
    const float* W1     = (const float*)d_in[6];
    const float* b1     = (const float*)d_in[7];
    const float* W2     = (const float*)d_in[8];
    const float* b2     = (const float*)d_in[9];
    const float* mask   = (const float*)d_in[10];
    const float* avg    = (const float*)d_in[11];
    float* out = (float*)d_out;

    static int configured = 0;
    if (!configured) {
        cudaFuncSetAttribute(gemm_tf32_kernel,
                             cudaFuncAttributeMaxDynamicSharedMemorySize, SMEM_GEMM);
        configured = 1;
    }

    gating_kernel<<<B_, 256>>>(inputs, Wg, bg);
    hidden_kernel<<<1, 256>>>(avg, W1, b1);
    conn_kernel<<<U_ / 256, 256>>>(W2, b2, mask);
    xt_kernel<<<(B_ * D_) / 256, 256>>>(inputs);
    wt_kernel<<<dim3(D_ / 16, U_ / 32), 256>>>(w, delay);
    gemm_tf32_kernel<<<dim3(B_ / BM, U_ / BN), 256, SMEM_GEMM>>>(bias, out);
}

// round 8
// speedup vs baseline: 1.6272x; 1.6272x over previous
#include <cuda_runtime.h>
#include <math.h>
#include <stdint.h>

#define B_   1024
#define D_   2048
#define U_   4096
#define BR_  4
#define HID_ 32
#define K_   (D_ * BR_)   // 8192

#define BM 128
#define BN 128
#define BK 32
#define NITER (K_ / BK)   // 256
#define ROWB  144         // 32 floats (128B) + 16B pad: conflict-free LDSM
#define ASZ   (BM * ROWB)             // 18432
#define BSZ   (BN * ROWB)             // 18432
#define STAGE (ASZ + BSZ)             // 36864
#define SMEM_GEMM (STAGE * 2)         // 73728

// ---------------- device scratch (static, allocation-free) ----------------
__device__ float g_gate[B_ * BR_];      // softmax gating [B,4]
__device__ float g_hid[HID_];           // MLP hidden [32]
__device__ float g_cm[U_];              // connectivity * mask [U]
__device__ float g_xt[B_ * K_];         // A: [B, K] K-major, tf32-rounded
__device__ float g_wt[(size_t)U_ * K_]; // B: [U, K] K-major, tf32-rounded

// ---------------- helpers ----------------
__device__ __forceinline__ float tf32_rna(float x) {
    float r; asm("cvt.rna.tf32.f32 %0, %1;" : "=f"(r) : "f"(x)); return r;
}
__device__ __forceinline__ uint32_t smem_u32(const void* p) {
    uint32_t a;
    asm("{ .reg .u64 t; cvta.to.shared.u64 t, %1; cvt.u32.u64 %0, t; }" : "=r"(a) : "l"(p));
    return a;
}
__device__ __forceinline__ void cp_async16(uint32_t dst, const void* src) {
    asm volatile("cp.async.cg.shared.global [%0], [%1], 16;\n" :: "r"(dst), "l"(src));
}
template <int N> __device__ __forceinline__ void cp_wait() {
    asm volatile("cp.async.wait_group %0;\n" :: "n"(N) : "memory");
}
__device__ __forceinline__ void ldsm_x4(uint32_t& r0, uint32_t& r1, uint32_t& r2,
                                        uint32_t& r3, uint32_t addr) {
    asm volatile("ldmatrix.sync.aligned.m8n8.x4.shared.b16 {%0,%1,%2,%3}, [%4];"
                 : "=r"(r0), "=r"(r1), "=r"(r2), "=r"(r3) : "r"(addr));
}
__device__ __forceinline__ void mma_tf32(float& c0, float& c1, float& c2, float& c3,
                                         uint32_t a0, uint32_t a1, uint32_t a2, uint32_t a3,
                                         uint32_t b0, uint32_t b1) {
    asm volatile(
        "mma.sync.aligned.m16n8k8.row.col.f32.tf32.tf32.f32 "
        "{%0,%1,%2,%3}, {%4,%5,%6,%7}, {%8,%9}, {%0,%1,%2,%3};\n"
        : "+f"(c0), "+f"(c1), "+f"(c2), "+f"(c3)
        : "r"(a0), "r"(a1), "r"(a2), "r"(a3), "r"(b0), "r"(b1));
}

// ---------------- K1: gating = softmax(x @ Wg + bg) over 4 branches -------
__global__ void gating_kernel(const float* __restrict__ x,
                              const float* __restrict__ Wg,
                              const float* __restrict__ bg) {
    int b = blockIdx.x, tid = threadIdx.x;
    const float* xr = x + b * D_;
    float p0 = 0.f, p1 = 0.f, p2 = 0.f, p3 = 0.f;
    for (int d = tid; d < D_; d += 256) {
        float xv = xr[d];
        float4 wv = *(const float4*)(Wg + d * 4);
        p0 += xv * wv.x; p1 += xv * wv.y; p2 += xv * wv.z; p3 += xv * wv.w;
    }
    __shared__ float s[256][4];
    s[tid][0] = p0; s[tid][1] = p1; s[tid][2] = p2; s[tid][3] = p3;
    __syncthreads();
    for (int off = 128; off > 0; off >>= 1) {
        if (tid < off) {
            #pragma unroll
            for (int k = 0; k < 4; k++) s[tid][k] += s[tid + off][k];
        }
        __syncthreads();
    }
    if (tid == 0) {
        float l[4], m = -1e30f;
        #pragma unroll
        for (int k = 0; k < 4; k++) { l[k] = s[0][k] + bg[k]; m = fmaxf(m, l[k]); }
        float e[4], sum = 0.f;
        #pragma unroll
        for (int k = 0; k < 4; k++) { e[k] = expf(l[k] - m); sum += e[k]; }
        float inv = 1.f / sum;
        #pragma unroll
        for (int k = 0; k < 4; k++) g_gate[b * 4 + k] = e[k] * inv;
    }
}

// ---------------- K2: h = relu(avg @ W1 + b1), [32] ----------------------
__global__ void hidden_kernel(const float* __restrict__ avg,
                              const float* __restrict__ W1,
                              const float* __restrict__ b1) {
    int tid = threadIdx.x;
    int j = tid & 31, grp = tid >> 5;
    float p = 0.f;
    for (int u = grp; u < U_; u += 8)
        p += avg[u] * W1[u * HID_ + j];
    __shared__ float s[8][32];
    s[grp][j] = p;
    __syncthreads();
    if (grp == 0) {
        float sum = 0.f;
        #pragma unroll
        for (int g = 0; g < 8; g++) sum += s[g][j];
        g_hid[j] = fmaxf(sum + b1[j], 0.f);
    }
}

// ---------------- K3: cm = sigmoid(h @ W2 + b2) * mask, [U] --------------
__global__ void conn_kernel(const float* __restrict__ W2,
                            const float* __restrict__ b2,
                            const float* __restrict__ mask) {
    __shared__ float h[HID_];
    int tid = threadIdx.x;
    if (tid < HID_) h[tid] = g_hid[tid];
    __syncthreads();
    int u = blockIdx.x * 256 + tid;
    float acc = b2[u];
    #pragma unroll
    for (int j = 0; j < HID_; j++) acc += h[j] * W2[j * U_ + u];
    g_cm[u] = mask[u] / (1.f + expf(-acc));
}

// ---------------- K4: x~[b, 4d+k] = tf32(x[b,d] * g[b,k]) ----------------
__global__ void xt_kernel(const float* __restrict__ x) {
    int idx = blockIdx.x * 256 + threadIdx.x;   // over B*D
    int b = idx >> 11;
    float xv = x[idx];
    float4 gv = *(const float4*)(g_gate + b * 4);
    float4 o;
    o.x = tf32_rna(xv * gv.x); o.y = tf32_rna(xv * gv.y);
    o.z = tf32_rna(xv * gv.z); o.w = tf32_rna(xv * gv.w);
    *(float4*)(g_xt + (size_t)idx * 4) = o;
}

// ------- K5: W~[u][4d+k] = tf32(w[d,u,k]*sigmoid(delay)), smem transpose --
// block: 16 d x 32 u tile; skips blocks whose entire u-range is masked
// (stale/zero g_wt there is multiplied by cm==0 in the GEMM epilogue).
__global__ void wt_kernel(const float* __restrict__ w,
                          const float* __restrict__ delay) {
    int d0 = blockIdx.x * 16, u0 = blockIdx.y * 32;
    int tid = threadIdx.x;
    float cmv = g_cm[u0 + (tid & 31)];
    if (!__syncthreads_or(cmv != 0.f)) return;

    __shared__ float s[16][132];
    #pragma unroll
    for (int i = 0; i < 8; i++) {
        int idx = i * 256 + tid;
        int dl = idx >> 7, c = idx & 127;          // c = u_l*4 + k
        size_t g = (size_t)(d0 + dl) * (U_ * BR_) + (size_t)u0 * 4 + c;
        float wv = w[g], dv = delay[g];
        s[dl][c] = tf32_rna(wv / (1.f + __expf(-dv)));
    }
    __syncthreads();
    #pragma unroll
    for (int i = 0; i < 8; i++) {
        int idx = i * 256 + tid;
        int ul = idx >> 6, q = idx & 63;           // q = d_l*4 + k
        g_wt[(size_t)(u0 + ul) * K_ + d0 * 4 + q] = s[q >> 2][ul * 4 + (q & 3)];
    }
}

// ---------------- K6: tf32 mma.sync GEMM, ldmatrix path, occ-2 -----------
__device__ __forceinline__ void load_stage(uint32_t stagebase, int chunk,
                                           int bm, int bn, int tid) {
    // A: 128 rows x 128B (8 chunks of 16B) -> 4 cp per thread
    #pragma unroll
    for (int i = 0; i < 4; i++) {
        int id = i * 256 + tid;
        int row = id >> 3, c = id & 7;
        cp_async16(stagebase + row * ROWB + c * 16,
                   g_xt + (size_t)(bm * BM + row) * K_ + chunk * BK + c * 4);
    }
    // B: 128 rows x 128B -> 4 cp per thread
    #pragma unroll
    for (int i = 0; i < 4; i++) {
        int id = i * 256 + tid;
        int row = id >> 3, c = id & 7;
        cp_async16(stagebase + ASZ + row * ROWB + c * 16,
                   g_wt + (size_t)(bn * BN + row) * K_ + chunk * BK + c * 4);
    }
    asm volatile("cp.async.commit_group;\n" ::: "memory");
}

__global__ __launch_bounds__(256, 2)
void gemm_tf32_kernel(const float* __restrict__ bias, float* __restrict__ out) {
    extern __shared__ char smem[];
    const uint32_t sb = smem_u32(smem);
    const int tid = threadIdx.x, wid = tid >> 5, lane = tid & 31;
    const int bm = blockIdx.x, bn = blockIdx.y;

    // --- data-driven tile skip over 128-wide N tile ---
    float cmv = (tid < 128) ? g_cm[bn * BN + tid] : 0.f;
    if (!__syncthreads_or(cmv != 0.f)) {
        int col4 = (tid & 31) * 4;
        int r0 = tid >> 5;
        float4 z = make_float4(0.f, 0.f, 0.f, 0.f);
        #pragma unroll
        for (int r = 0; r < 16; r++) {
            int row = bm * BM + r0 + r * 8;
            *(float4*)(out + (size_t)row * U_ + bn * BN + col4) = z;
        }
        return;
    }

    const int wm = (wid >> 2) * 64;       // warp M offset (2 warp-rows)
    const int wn = (wid & 3) * 32;        // warp N offset (4 warp-cols)
    const int r8 = lane & 7;
    const int half = (lane >> 3) & 1;
    const int kh = lane >> 4;
    const uint32_t aoff = (uint32_t)((wm + half * 8 + r8) * ROWB + kh * 16);
    const uint32_t boff = (uint32_t)(ASZ + (wn + half * 8 + r8) * ROWB + kh * 16);

    float acc[4][4][4];
    #pragma unroll
    for (int i = 0; i < 4; i++)
        #pragma unroll
        for (int j = 0; j < 4; j++)
            #pragma unroll
            for (int r = 0; r < 4; r++) acc[i][j][r] = 0.f;

    // prologue: stages 0,1
    load_stage(sb, 0, bm, bn, tid);
    load_stage(sb + STAGE, 1, bm, bn, tid);

    for (int t = 0; t < NITER; t++) {
        cp_wait<1>();
        __syncthreads();
        const uint32_t stage = (t & 1) ? STAGE : 0;
        const uint32_t abase = sb + stage + aoff;
        const uint32_t bbase = sb + stage + boff;

        #pragma unroll
        for (int ks = 0; ks < 4; ks++) {
            uint32_t a[4][4], b[2][4];
            #pragma unroll
            for (int mi = 0; mi < 4; mi++)
                ldsm_x4(a[mi][0], a[mi][1], a[mi][2], a[mi][3],
                        abase + mi * (16 * ROWB) + ks * 32);
            #pragma unroll
            for (int h = 0; h < 2; h++)
                ldsm_x4(b[h][0], b[h][1], b[h][2], b[h][3],
                        bbase + h * (16 * ROWB) + ks * 32);
            #pragma unroll
            for (int mi = 0; mi < 4; mi++) {
                #pragma unroll
                for (int h = 0; h < 2; h++) {
                    mma_tf32(acc[mi][2*h][0], acc[mi][2*h][1],
                             acc[mi][2*h][2], acc[mi][2*h][3],
                             a[mi][0], a[mi][1], a[mi][2], a[mi][3],
                             b[h][0], b[h][2]);
                    mma_tf32(acc[mi][2*h+1][0], acc[mi][2*h+1][1],
                             acc[mi][2*h+1][2], acc[mi][2*h+1][3],
                             a[mi][0], a[mi][1], a[mi][2], a[mi][3],
                             b[h][1], b[h][3]);
                }
            }
        }
        __syncthreads();
        if (t + 2 < NITER)
            load_stage(sb + stage, t + 2, bm, bn, tid);
    }

    // --- epilogue: + sum_k gate[b,k]*bias[u,k], * cm[u], relu ---
    const int g = lane >> 2, tig = lane & 3;
    #pragma unroll
    for (int ni = 0; ni < 4; ni++) {
        int u0 = bn * BN + wn + ni * 8 + 2 * tig;
        float cm0 = g_cm[u0], cm1 = g_cm[u0 + 1];
        float4 bs0 = *(const float4*)(bias + (size_t)u0 * 4);
        float4 bs1 = *(const float4*)(bias + (size_t)(u0 + 1) * 4);
        #pragma unroll
        for (int mi = 0; mi < 4; mi++) {
            int r0 = bm * BM + wm + mi * 16 + g;
            int r1 = r0 + 8;
            float4 g0 = *(const float4*)(g_gate + r0 * 4);
            float4 g1 = *(const float4*)(g_gate + r1 * 4);
            float v0 = acc[mi][ni][0] + g0.x * bs0.x + g0.y * bs0.y + g0.z * bs0.z + g0.w * bs0.w;
            float v1 = acc[mi][ni][1] + g0.x * bs1.x + g0.y * bs1.y + g0.z * bs1.z + g0.w * bs1.w;
            float v2 = acc[mi][ni][2] + g1.x * bs0.x + g1.y * bs0.y + g1.z * bs0.z + g1.w * bs0.w;
            float v3 = acc[mi][ni][3] + g1.x * bs1.x + g1.y * bs1.y + g1.z * bs1.z + g1.w * bs1.w;
            *(float2*)(out + (size_t)r0 * U_ + u0) =
                make_float2(fmaxf(v0 * cm0, 0.f), fmaxf(v1 * cm1, 0.f));
            *(float2*)(out + (size_t)r1 * U_ + u0) =
                make_float2(fmaxf(v2 * cm0, 0.f), fmaxf(v3 * cm1, 0.f));
        }
    }
}

// ---------------- launch ----------------
extern "C" void kernel_launch(void* const* d_in, const int* in_sizes, int n_in,
                              void* d_out, int out_size) {
    const float* inputs = (const float*)d_in[0];
    const float* w      = (const float*)d_in[1];
    const float* bias   = (const float*)d_in[2];
    const float* delay  = (const float*)d_in[3];
    const float* Wg     = (const float*)d_in[4];
    const float* bg     = (const float*)d_in[5];
    const float* W1     = (const float*)d_in[6];
    const float* b1     = (const float*)d_in[7];
    const float* W2     = (const float*)d_in[8];
    const float* b2     = (const float*)d_in[9];
    const float* mask   = (const float*)d_in[10];
    const float* avg    = (const float*)d_in[11];
    float* out = (float*)d_out;

    static int configured = 0;
    if (!configured) {
        cudaFuncSetAttribute(gemm_tf32_kernel,
                             cudaFuncAttributeMaxDynamicSharedMemorySize, SMEM_GEMM);
        configured = 1;
    }

    gating_kernel<<<B_, 256>>>(inputs, Wg, bg);
    hidden_kernel<<<1, 256>>>(avg, W1, b1);
    conn_kernel<<<U_ / 256, 256>>>(W2, b2, mask);
    xt_kernel<<<(B_ * D_) / 256, 256>>>(inputs);
    wt_kernel<<<dim3(D_ / 16, U_ / 32), 256>>>(w, delay);
    gemm_tf32_kernel<<<dim3(B_ / BM, U_ / BN), 256, SMEM_GEMM>>>(bias, out);
}

// round 11
// speedup vs baseline: 2.6131x; 1.6058x over previous
#include <cuda_runtime.h>
#include <cuda_fp16.h>
#include <math.h>
#include <stdint.h>

#define B_   1024
#define D_   2048
#define U_   4096
#define BR_  4
#define HID_ 32
#define K_   (D_ * BR_)   // 8192

#define BM 128
#define BN 128
#define BK 64             // fp16 elements per stage chunk (128 bytes)
#define NITER (K_ / BK)   // 128
#define ROWB  144         // 128B row + 16B pad: conflict-free LDSM
#define ASZ   (BM * ROWB)             // 18432
#define STAGE (2 * ASZ)               // 36864 (A + B)
#define SMEM_GEMM (STAGE * 2)         // 73728

// ---------------- device scratch (static, allocation-free) ----------------
__device__ float  g_gate[B_ * BR_];      // softmax gating [B,4]
__device__ float  g_hid[HID_];           // MLP hidden [32]
__device__ float  g_cm[U_];              // connectivity * mask [U]
__device__ __half g_xt[B_ * K_];         // A: [B, K] K-major, fp16
__device__ __half g_wt[(size_t)U_ * K_]; // B: [U, K] K-major, fp16

// ---------------- helpers ----------------
__device__ __forceinline__ uint32_t smem_u32(const void* p) {
    uint32_t a;
    asm("{ .reg .u64 t; cvta.to.shared.u64 t, %1; cvt.u32.u64 %0, t; }" : "=r"(a) : "l"(p));
    return a;
}
__device__ __forceinline__ void cp_async16(uint32_t dst, const void* src) {
    asm volatile("cp.async.cg.shared.global [%0], [%1], 16;\n" :: "r"(dst), "l"(src));
}
template <int N> __device__ __forceinline__ void cp_wait() {
    asm volatile("cp.async.wait_group %0;\n" :: "n"(N) : "memory");
}
__device__ __forceinline__ void ldsm_x4(uint32_t& r0, uint32_t& r1, uint32_t& r2,
                                        uint32_t& r3, uint32_t addr) {
    asm volatile("ldmatrix.sync.aligned.m8n8.x4.shared.b16 {%0,%1,%2,%3}, [%4];"
                 : "=r"(r0), "=r"(r1), "=r"(r2), "=r"(r3) : "r"(addr));
}
__device__ __forceinline__ void mma_f16(float& c0, float& c1, float& c2, float& c3,
                                        uint32_t a0, uint32_t a1, uint32_t a2, uint32_t a3,
                                        uint32_t b0, uint32_t b1) {
    asm volatile(
        "mma.sync.aligned.m16n8k16.row.col.f32.f16.f16.f32 "
        "{%0,%1,%2,%3}, {%4,%5,%6,%7}, {%8,%9}, {%0,%1,%2,%3};\n"
        : "+f"(c0), "+f"(c1), "+f"(c2), "+f"(c3)
        : "r"(a0), "r"(a1), "r"(a2), "r"(a3), "r"(b0), "r"(b1));
}

// ---------------- K1: gating = softmax(x @ Wg + bg) over 4 branches -------
__global__ void gating_kernel(const float* __restrict__ x,
                              const float* __restrict__ Wg,
                              const float* __restrict__ bg) {
    int b = blockIdx.x, tid = threadIdx.x;
    const float* xr = x + b * D_;
    float p0 = 0.f, p1 = 0.f, p2 = 0.f, p3 = 0.f;
    for (int d = tid; d < D_; d += 256) {
        float xv = xr[d];
        float4 wv = *(const float4*)(Wg + d * 4);
        p0 += xv * wv.x; p1 += xv * wv.y; p2 += xv * wv.z; p3 += xv * wv.w;
    }
    __shared__ float s[256][4];
    s[tid][0] = p0; s[tid][1] = p1; s[tid][2] = p2; s[tid][3] = p3;
    __syncthreads();
    for (int off = 128; off > 0; off >>= 1) {
        if (tid < off) {
            #pragma unroll
            for (int k = 0; k < 4; k++) s[tid][k] += s[tid + off][k];
        }
        __syncthreads();
    }
    if (tid == 0) {
        float l[4], m = -1e30f;
        #pragma unroll
        for (int k = 0; k < 4; k++) { l[k] = s[0][k] + bg[k]; m = fmaxf(m, l[k]); }
        float e[4], sum = 0.f;
        #pragma unroll
        for (int k = 0; k < 4; k++) { e[k] = expf(l[k] - m); sum += e[k]; }
        float inv = 1.f / sum;
        #pragma unroll
        for (int k = 0; k < 4; k++) g_gate[b * 4 + k] = e[k] * inv;
    }
}

// ---------------- K2: h = relu(avg @ W1 + b1), [32] ----------------------
__global__ void hidden_kernel(const float* __restrict__ avg,
                              const float* __restrict__ W1,
                              const float* __restrict__ b1) {
    int tid = threadIdx.x;
    int j = tid & 31, grp = tid >> 5;
    float p = 0.f;
    for (int u = grp; u < U_; u += 8)
        p += avg[u] * W1[u * HID_ + j];
    __shared__ float s[8][32];
    s[grp][j] = p;
    __syncthreads();
    if (grp == 0) {
        float sum = 0.f;
        #pragma unroll
        for (int g = 0; g < 8; g++) sum += s[g][j];
        g_hid[j] = fmaxf(sum + b1[j], 0.f);
    }
}

// ---------------- K3: cm = sigmoid(h @ W2 + b2) * mask, [U] --------------
__global__ void conn_kernel(const float* __restrict__ W2,
                            const float* __restrict__ b2,
                            const float* __restrict__ mask) {
    __shared__ float h[HID_];
    int tid = threadIdx.x;
    if (tid < HID_) h[tid] = g_hid[tid];
    __syncthreads();
    int u = blockIdx.x * 256 + tid;
    float acc = b2[u];
    #pragma unroll
    for (int j = 0; j < HID_; j++) acc += h[j] * W2[j * U_ + u];
    g_cm[u] = mask[u] / (1.f + expf(-acc));
}

// ---------------- K4: x~[b, 4d+k] = fp16(x[b,d] * g[b,k]) ----------------
__global__ void xt_kernel(const float* __restrict__ x) {
    int idx = blockIdx.x * 256 + threadIdx.x;   // over B*D
    int b = idx >> 11;
    float xv = x[idx];
    float4 gv = *(const float4*)(g_gate + b * 4);
    __half2 h01 = __floats2half2_rn(xv * gv.x, xv * gv.y);
    __half2 h23 = __floats2half2_rn(xv * gv.z, xv * gv.w);
    uint2 o;
    o.x = *(uint32_t*)&h01;
    o.y = *(uint32_t*)&h23;
    *(uint2*)(g_xt + (size_t)idx * 4) = o;
}

// ------- K5: W~[u][4d+k] = fp16(w[d,u,k]*sigmoid(delay)), smem transpose --
// block: 16 d x 32 u tile; skips blocks whose entire u-range is masked
// (stale/zero g_wt there is multiplied by cm==0 in the GEMM epilogue).
__global__ void wt_kernel(const float* __restrict__ w,
                          const float* __restrict__ delay) {
    int d0 = blockIdx.x * 16, u0 = blockIdx.y * 32;
    int tid = threadIdx.x;
    float cmv = g_cm[u0 + (tid & 31)];
    if (!__syncthreads_or(cmv != 0.f)) return;

    __shared__ float s[16][132];
    #pragma unroll
    for (int i = 0; i < 8; i++) {
        int idx = i * 256 + tid;
        int dl = idx >> 7, c = idx & 127;          // c = u_l*4 + k
        size_t g = (size_t)(d0 + dl) * (U_ * BR_) + (size_t)u0 * 4 + c;
        float wv = w[g], dv = delay[g];
        s[dl][c] = wv / (1.f + __expf(-dv));
    }
    __syncthreads();
    // write 32 u-rows x 64 k as half2 (1024 half2 / 256 threads = 4 each)
    #pragma unroll
    for (int i = 0; i < 4; i++) {
        int idx = i * 256 + tid;
        int ul = idx >> 5, p = idx & 31;           // p = half2 index (q = 2p)
        int dl = p >> 1, kb = (p & 1) * 2;         // q>>2, (2p)&3
        __half2 hv = __floats2half2_rn(s[dl][ul * 4 + kb], s[dl][ul * 4 + kb + 1]);
        *(__half2*)(g_wt + (size_t)(u0 + ul) * K_ + d0 * 4 + 2 * p) = hv;
    }
}

// ---------------- K6: fp16 mma.sync GEMM, ldmatrix path, occ-2 -----------
__device__ __forceinline__ void load_stage(uint32_t stagebase, int chunk,
                                           int bm, int bn, int tid) {
    // A: 128 rows x 128B (8 chunks of 16B) -> 4 cp per thread
    #pragma unroll
    for (int i = 0; i < 4; i++) {
        int id = i * 256 + tid;
        int row = id >> 3, c = id & 7;
        cp_async16(stagebase + row * ROWB + c * 16,
                   g_xt + (size_t)(bm * BM + row) * K_ + chunk * BK + c * 8);
    }
    // B: 128 rows x 128B -> 4 cp per thread
    #pragma unroll
    for (int i = 0; i < 4; i++) {
        int id = i * 256 + tid;
        int row = id >> 3, c = id & 7;
        cp_async16(stagebase + ASZ + row * ROWB + c * 16,
                   g_wt + (size_t)(bn * BN + row) * K_ + chunk * BK + c * 8);
    }
    asm volatile("cp.async.commit_group;\n" ::: "memory");
}

__global__ __launch_bounds__(256, 2)
void gemm_f16_kernel(const float* __restrict__ bias, float* __restrict__ out) {
    extern __shared__ char smem[];
    const uint32_t sb = smem_u32(smem);
    const int tid = threadIdx.x, wid = tid >> 5, lane = tid & 31;
    const int bm = blockIdx.x, bn = blockIdx.y;

    // --- data-driven tile skip over 128-wide N tile ---
    float cmv = (tid < 128) ? g_cm[bn * BN + tid] : 0.f;
    if (!__syncthreads_or(cmv != 0.f)) {
        int col4 = (tid & 31) * 4;
        int r0 = tid >> 5;
        float4 z = make_float4(0.f, 0.f, 0.f, 0.f);
        #pragma unroll
        for (int r = 0; r < 16; r++) {
            int row = bm * BM + r0 + r * 8;
            *(float4*)(out + (size_t)row * U_ + bn * BN + col4) = z;
        }
        return;
    }

    const int wm = (wid >> 2) * 64;       // warp M offset (2 warp-rows)
    const int wn = (wid & 3) * 32;        // warp N offset (4 warp-cols)
    const int r8 = lane & 7;
    const int half = (lane >> 3) & 1;     // +8 rows for matrices 1,3
    const int kh = lane >> 4;             // +16B (k+8) for matrices 2,3
    const uint32_t aoff = (uint32_t)((wm + half * 8 + r8) * ROWB + kh * 16);
    const uint32_t boff = (uint32_t)(ASZ + (wn + half * 8 + r8) * ROWB + kh * 16);

    float acc[4][4][4];
    #pragma unroll
    for (int i = 0; i < 4; i++)
        #pragma unroll
        for (int j = 0; j < 4; j++)
            #pragma unroll
            for (int r = 0; r < 4; r++) acc[i][j][r] = 0.f;

    // prologue: stages 0,1
    load_stage(sb, 0, bm, bn, tid);
    load_stage(sb + STAGE, 1, bm, bn, tid);

    for (int t = 0; t < NITER; t++) {
        cp_wait<1>();
        __syncthreads();
        const uint32_t stage = (t & 1) ? STAGE : 0;
        const uint32_t abase = sb + stage + aoff;
        const uint32_t bbase = sb + stage + boff;

        #pragma unroll
        for (int ks = 0; ks < 4; ks++) {   // 4 k16 steps per BK=64
            uint32_t a[4][4], b[2][4];
            #pragma unroll
            for (int mi = 0; mi < 4; mi++)
                ldsm_x4(a[mi][0], a[mi][1], a[mi][2], a[mi][3],
                        abase + mi * (16 * ROWB) + ks * 32);
            #pragma unroll
            for (int h = 0; h < 2; h++)
                ldsm_x4(b[h][0], b[h][1], b[h][2], b[h][3],
                        bbase + h * (16 * ROWB) + ks * 32);
            // fragments: a = {m0-7/k0-7, m8-15/k0-7, m0-7/k8-15, m8-15/k8-15}
            //            b[h] = {n0-7/k0-7, n8-15/k0-7, n0-7/k8-15, n8-15/k8-15}
            #pragma unroll
            for (int mi = 0; mi < 4; mi++) {
                #pragma unroll
                for (int h = 0; h < 2; h++) {
                    mma_f16(acc[mi][2*h][0], acc[mi][2*h][1],
                            acc[mi][2*h][2], acc[mi][2*h][3],
                            a[mi][0], a[mi][1], a[mi][2], a[mi][3],
                            b[h][0], b[h][2]);
                    mma_f16(acc[mi][2*h+1][0], acc[mi][2*h+1][1],
                            acc[mi][2*h+1][2], acc[mi][2*h+1][3],
                            a[mi][0], a[mi][1], a[mi][2], a[mi][3],
                            b[h][1], b[h][3]);
                }
            }
        }
        __syncthreads();
        if (t + 2 < NITER)
            load_stage(sb + stage, t + 2, bm, bn, tid);
    }

    // --- epilogue: + sum_k gate[b,k]*bias[u,k], * cm[u], relu ---
    const int g = lane >> 2, tig = lane & 3;
    #pragma unroll
    for (int ni = 0; ni < 4; ni++) {
        int u0 = bn * BN + wn + ni * 8 + 2 * tig;
        float cm0 = g_cm[u0], cm1 = g_cm[u0 + 1];
        float4 bs0 = *(const float4*)(bias + (size_t)u0 * 4);
        float4 bs1 = *(const float4*)(bias + (size_t)(u0 + 1) * 4);
        #pragma unroll
        for (int mi = 0; mi < 4; mi++) {
            int r0 = bm * BM + wm + mi * 16 + g;
            int r1 = r0 + 8;
            float4 g0 = *(const float4*)(g_gate + r0 * 4);
            float4 g1 = *(const float4*)(g_gate + r1 * 4);
            float v0 = acc[mi][ni][0] + g0.x * bs0.x + g0.y * bs0.y + g0.z * bs0.z + g0.w * bs0.w;
            float v1 = acc[mi][ni][1] + g0.x * bs1.x + g0.y * bs1.y + g0.z * bs1.z + g0.w * bs1.w;
            float v2 = acc[mi][ni][2] + g1.x * bs0.x + g1.y * bs0.y + g1.z * bs0.z + g1.w * bs0.w;
            float v3 = acc[mi][ni][3] + g1.x * bs1.x + g1.y * bs1.y + g1.z * bs1.z + g1.w * bs1.w;
            *(float2*)(out + (size_t)r0 * U_ + u0) =
                make_float2(fmaxf(v0 * cm0, 0.f), fmaxf(v1 * cm1, 0.f));
            *(float2*)(out + (size_t)r1 * U_ + u0) =
                make_float2(fmaxf(v2 * cm0, 0.f), fmaxf(v3 * cm1, 0.f));
        }
    }
}

// ---------------- launch ----------------
extern "C" void kernel_launch(void* const* d_in, const int* in_sizes, int n_in,
                              void* d_out, int out_size) {
    const float* inputs = (const float*)d_in[0];
    const float* w      = (const float*)d_in[1];
    const float* bias   = (const float*)d_in[2];
    const float* delay  = (const float*)d_in[3];
    const float* Wg     = (const float*)d_in[4];
    const float* bg     = (const float*)d_in[5];
    const float* W1     = (const float*)d_in[6];
    const float* b1     = (const float*)d_in[7];
    const float* W2     = (const float*)d_in[8];
    const float* b2     = (const float*)d_in[9];
    const float* mask   = (const float*)d_in[10];
    const float* avg    = (const float*)d_in[11];
    float* out = (float*)d_out;

    static int configured = 0;
    if (!configured) {
        cudaFuncSetAttribute(gemm_f16_kernel,
                             cudaFuncAttributeMaxDynamicSharedMemorySize, SMEM_GEMM);
        configured = 1;
    }

    gating_kernel<<<B_, 256>>>(inputs, Wg, bg);
    hidden_kernel<<<1, 256>>>(avg, W1, b1);
    conn_kernel<<<U_ / 256, 256>>>(W2, b2, mask);
    xt_kernel<<<(B_ * D_) / 256, 256>>>(inputs);
    wt_kernel<<<dim3(D_ / 16, U_ / 32), 256>>>(w, delay);
    gemm_f16_kernel<<<dim3(B_ / BM, U_ / BN), 256, SMEM_GEMM>>>(bias, out);
}

// round 13
// speedup vs baseline: 2.7817x; 1.0645x over previous
#include <cuda_runtime.h>
#include <cuda_fp16.h>
#include <math.h>
#include <stdint.h>

#define B_   1024
#define D_   2048
#define U_   4096
#define BR_  4
#define HID_ 32
#define K_   (D_ * BR_)   // 8192

#define BM 128
#define BN 128
#define BK 64             // fp16 elements per stage chunk (128 bytes)
#define NITER (K_ / BK)   // 128
#define ROWB  144         // 128B row + 16B pad: conflict-free LDSM
#define ASZ   (BM * ROWB)             // 18432
#define STAGE (2 * ASZ)               // 36864 (A + B)
#define SMEM_GEMM (STAGE * 2)         // 73728

// ---------------- device scratch (static, allocation-free) ----------------
__device__ float  g_gate[B_ * BR_];      // softmax gating [B,4]
__device__ float  g_hid[HID_];           // MLP hidden [32]
__device__ float  g_cm[U_];              // connectivity * mask [U]
__device__ __half g_xt[B_ * K_];         // A: [B, K] K-major, fp16
__device__ __half g_wt[(size_t)U_ * K_]; // B: [U, K] K-major, fp16

// ---------------- helpers ----------------
__device__ __forceinline__ uint32_t smem_u32(const void* p) {
    uint32_t a;
    asm("{ .reg .u64 t; cvta.to.shared.u64 t, %1; cvt.u32.u64 %0, t; }" : "=r"(a) : "l"(p));
    return a;
}
__device__ __forceinline__ void cp_async16(uint32_t dst, const void* src) {
    asm volatile("cp.async.cg.shared.global [%0], [%1], 16;\n" :: "r"(dst), "l"(src));
}
template <int N> __device__ __forceinline__ void cp_wait() {
    asm volatile("cp.async.wait_group %0;\n" :: "n"(N) : "memory");
}
__device__ __forceinline__ void ldsm_x4(uint32_t& r0, uint32_t& r1, uint32_t& r2,
                                        uint32_t& r3, uint32_t addr) {
    asm volatile("ldmatrix.sync.aligned.m8n8.x4.shared.b16 {%0,%1,%2,%3}, [%4];"
                 : "=r"(r0), "=r"(r1), "=r"(r2), "=r"(r3) : "r"(addr));
}
__device__ __forceinline__ void mma_f16(float& c0, float& c1, float& c2, float& c3,
                                        uint32_t a0, uint32_t a1, uint32_t a2, uint32_t a3,
                                        uint32_t b0, uint32_t b1) {
    asm volatile(
        "mma.sync.aligned.m16n8k16.row.col.f32.f16.f16.f32 "
        "{%0,%1,%2,%3}, {%4,%5,%6,%7}, {%8,%9}, {%0,%1,%2,%3};\n"
        : "+f"(c0), "+f"(c1), "+f"(c2), "+f"(c3)
        : "r"(a0), "r"(a1), "r"(a2), "r"(a3), "r"(b0), "r"(b1));
}

// -------- K1 (fused): gate = softmax(x@Wg+bg); x~[b,4d+k] = fp16(x*g) ----
__global__ void gating_xt_kernel(const float* __restrict__ x,
                                 const float* __restrict__ Wg,
                                 const float* __restrict__ bg) {
    int b = blockIdx.x, tid = threadIdx.x;
    __shared__ float xs[D_];
    __shared__ float s[256][4];
    __shared__ float gate_s[4];

    // cache x row (each thread 2 float4 = 8 floats)
    const float4* xr4 = (const float4*)(x + b * D_);
    #pragma unroll
    for (int i = 0; i < 2; i++) {
        int q = i * 256 + tid;
        *(float4*)(xs + q * 4) = xr4[q];
    }
    __syncthreads();

    // gate logits
    float p0 = 0.f, p1 = 0.f, p2 = 0.f, p3 = 0.f;
    for (int d = tid; d < D_; d += 256) {
        float xv = xs[d];
        float4 wv = *(const float4*)(Wg + d * 4);
        p0 += xv * wv.x; p1 += xv * wv.y; p2 += xv * wv.z; p3 += xv * wv.w;
    }
    s[tid][0] = p0; s[tid][1] = p1; s[tid][2] = p2; s[tid][3] = p3;
    __syncthreads();
    for (int off = 128; off > 0; off >>= 1) {
        if (tid < off) {
            #pragma unroll
            for (int k = 0; k < 4; k++) s[tid][k] += s[tid + off][k];
        }
        __syncthreads();
    }
    if (tid == 0) {
        float l[4], m = -1e30f;
        #pragma unroll
        for (int k = 0; k < 4; k++) { l[k] = s[0][k] + bg[k]; m = fmaxf(m, l[k]); }
        float e[4], sum = 0.f;
        #pragma unroll
        for (int k = 0; k < 4; k++) { e[k] = expf(l[k] - m); sum += e[k]; }
        float inv = 1.f / sum;
        #pragma unroll
        for (int k = 0; k < 4; k++) {
            gate_s[k] = e[k] * inv;
            g_gate[b * 4 + k] = e[k] * inv;
        }
    }
    __syncthreads();

    float g0 = gate_s[0], g1 = gate_s[1], g2 = gate_s[2], g3 = gate_s[3];
    #pragma unroll
    for (int i = 0; i < 8; i++) {
        int d = i * 256 + tid;
        float xv = xs[d];
        __half2 h01 = __floats2half2_rn(xv * g0, xv * g1);
        __half2 h23 = __floats2half2_rn(xv * g2, xv * g3);
        uint2 o;
        o.x = *(uint32_t*)&h01;
        o.y = *(uint32_t*)&h23;
        *(uint2*)(g_xt + (size_t)b * K_ + d * 4) = o;
    }
}

// ---------------- K2: h = relu(avg @ W1 + b1), [32] ----------------------
__global__ void hidden_kernel(const float* __restrict__ avg,
                              const float* __restrict__ W1,
                              const float* __restrict__ b1) {
    int tid = threadIdx.x;
    int j = tid & 31, grp = tid >> 5;
    float p = 0.f;
    for (int u = grp; u < U_; u += 8)
        p += avg[u] * W1[u * HID_ + j];
    __shared__ float s[8][32];
    s[grp][j] = p;
    __syncthreads();
    if (grp == 0) {
        float sum = 0.f;
        #pragma unroll
        for (int g = 0; g < 8; g++) sum += s[g][j];
        g_hid[j] = fmaxf(sum + b1[j], 0.f);
    }
}

// ---------------- K3: cm = sigmoid(h @ W2 + b2) * mask, [U] --------------
__global__ void conn_kernel(const float* __restrict__ W2,
                            const float* __restrict__ b2,
                            const float* __restrict__ mask) {
    __shared__ float h[HID_];
    int tid = threadIdx.x;
    if (tid < HID_) h[tid] = g_hid[tid];
    __syncthreads();
    int u = blockIdx.x * 256 + tid;
    float acc = b2[u];
    #pragma unroll
    for (int j = 0; j < HID_; j++) acc += h[j] * W2[j * U_ + u];
    g_cm[u] = mask[u] / (1.f + expf(-acc));
}

// ------- K5: W~[u][4d+k] = fp16(w[d,u,k]*sigmoid(delay)), smem transpose --
// block: 16 d x 32 u tile; float4 global loads (one d-row of the tile is
// 32 u * 4 k = 128 floats = 32 float4 -> 512 float4 total, 2 per thread);
// skips fully-masked u-blocks (stale/zero g_wt hits cm==0 in the epilogue).
__global__ void wt_kernel(const float* __restrict__ w,
                          const float* __restrict__ delay) {
    int d0 = blockIdx.x * 16, u0 = blockIdx.y * 32;
    int tid = threadIdx.x;
    float cmv = g_cm[u0 + (tid & 31)];
    if (!__syncthreads_or(cmv != 0.f)) return;

    __shared__ float s[16][136];   // 128 data floats + pad, 16B-aligned rows
    #pragma unroll
    for (int i = 0; i < 2; i++) {
        int idx = i * 256 + tid;                   // 0..511
        int dl = idx >> 5, c4 = idx & 31;          // d-row, float4-in-row
        size_t g = (size_t)(d0 + dl) * (U_ * BR_) + (size_t)u0 * 4 + c4 * 4;
        float4 wv = *(const float4*)(w + g);
        float4 dv = *(const float4*)(delay + g);
        float4 o;
        o.x = wv.x / (1.f + __expf(-dv.x));
        o.y = wv.y / (1.f + __expf(-dv.y));
        o.z = wv.z / (1.f + __expf(-dv.z));
        o.w = wv.w / (1.f + __expf(-dv.w));
        *(float4*)(&s[dl][c4 * 4]) = o;
    }
    __syncthreads();
    // write 32 u-rows x 64 k as half2 (1024 half2 / 256 threads = 4 each)
    #pragma unroll
    for (int i = 0; i < 4; i++) {
        int idx = i * 256 + tid;
        int ul = idx >> 5, p = idx & 31;           // p = half2 index (q = 2p)
        int dl = p >> 1, kb = (p & 1) * 2;
        __half2 hv = __floats2half2_rn(s[dl][ul * 4 + kb], s[dl][ul * 4 + kb + 1]);
        *(__half2*)(g_wt + (size_t)(u0 + ul) * K_ + d0 * 4 + 2 * p) = hv;
    }
}

// ---------------- K6: fp16 mma.sync GEMM, ldmatrix path, occ-2 -----------
// (byte-identical mainloop to the 406us round-11 kernel)
__device__ __forceinline__ void load_stage(uint32_t stagebase, int chunk,
                                           int bm, int bn, int tid) {
    #pragma unroll
    for (int i = 0; i < 4; i++) {
        int id = i * 256 + tid;
        int row = id >> 3, c = id & 7;
        cp_async16(stagebase + row * ROWB + c * 16,
                   g_xt + (size_t)(bm * BM + row) * K_ + chunk * BK + c * 8);
    }
    #pragma unroll
    for (int i = 0; i < 4; i++) {
        int id = i * 256 + tid;
        int row = id >> 3, c = id & 7;
        cp_async16(stagebase + ASZ + row * ROWB + c * 16,
                   g_wt + (size_t)(bn * BN + row) * K_ + chunk * BK + c * 8);
    }
    asm volatile("cp.async.commit_group;\n" ::: "memory");
}

__global__ __launch_bounds__(256, 2)
void gemm_f16_kernel(const float* __restrict__ bias, float* __restrict__ out) {
    extern __shared__ char smem[];
    const uint32_t sb = smem_u32(smem);
    const int tid = threadIdx.x, wid = tid >> 5, lane = tid & 31;
    const int bm = blockIdx.x, bn = blockIdx.y;

    float cmv = (tid < 128) ? g_cm[bn * BN + tid] : 0.f;
    if (!__syncthreads_or(cmv != 0.f)) {
        int col4 = (tid & 31) * 4;
        int r0 = tid >> 5;
        float4 z = make_float4(0.f, 0.f, 0.f, 0.f);
        #pragma unroll
        for (int r = 0; r < 16; r++) {
            int row = bm * BM + r0 + r * 8;
            *(float4*)(out + (size_t)row * U_ + bn * BN + col4) = z;
        }
        return;
    }

    const int wm = (wid >> 2) * 64;
    const int wn = (wid & 3) * 32;
    const int r8 = lane & 7;
    const int half = (lane >> 3) & 1;
    const int kh = lane >> 4;
    const uint32_t aoff = (uint32_t)((wm + half * 8 + r8) * ROWB + kh * 16);
    const uint32_t boff = (uint32_t)(ASZ + (wn + half * 8 + r8) * ROWB + kh * 16);

    float acc[4][4][4];
    #pragma unroll
    for (int i = 0; i < 4; i++)
        #pragma unroll
        for (int j = 0; j < 4; j++)
            #pragma unroll
            for (int r = 0; r < 4; r++) acc[i][j][r] = 0.f;

    load_stage(sb, 0, bm, bn, tid);
    load_stage(sb + STAGE, 1, bm, bn, tid);

    for (int t = 0; t < NITER; t++) {
        cp_wait<1>();
        __syncthreads();
        const uint32_t stage = (t & 1) ? STAGE : 0;
        const uint32_t abase = sb + stage + aoff;
        const uint32_t bbase = sb + stage + boff;

        #pragma unroll
        for (int ks = 0; ks < 4; ks++) {
            uint32_t a[4][4], b[2][4];
            #pragma unroll
            for (int mi = 0; mi < 4; mi++)
                ldsm_x4(a[mi][0], a[mi][1], a[mi][2], a[mi][3],
                        abase + mi * (16 * ROWB) + ks * 32);
            #pragma unroll
            for (int h = 0; h < 2; h++)
                ldsm_x4(b[h][0], b[h][1], b[h][2], b[h][3],
                        bbase + h * (16 * ROWB) + ks * 32);
            #pragma unroll
            for (int mi = 0; mi < 4; mi++) {
                #pragma unroll
                for (int h = 0; h < 2; h++) {
                    mma_f16(acc[mi][2*h][0], acc[mi][2*h][1],
                            acc[mi][2*h][2], acc[mi][2*h][3],
                            a[mi][0], a[mi][1], a[mi][2], a[mi][3],
                            b[h][0], b[h][2]);
                    mma_f16(acc[mi][2*h+1][0], acc[mi][2*h+1][1],
                            acc[mi][2*h+1][2], acc[mi][2*h+1][3],
                            a[mi][0], a[mi][1], a[mi][2], a[mi][3],
                            b[h][1], b[h][3]);
                }
            }
        }
        __syncthreads();
        if (t + 2 < NITER)
            load_stage(sb + stage, t + 2, bm, bn, tid);
    }

    const int g = lane >> 2, tig = lane & 3;
    #pragma unroll
    for (int ni = 0; ni < 4; ni++) {
        int u0 = bn * BN + wn + ni * 8 + 2 * tig;
        float cm0 = g_cm[u0], cm1 = g_cm[u0 + 1];
        float4 bs0 = *(const float4*)(bias + (size_t)u0 * 4);
        float4 bs1 = *(const float4*)(bias + (size_t)(u0 + 1) * 4);
        #pragma unroll
        for (int mi = 0; mi < 4; mi++) {
            int r0 = bm * BM + wm + mi * 16 + g;
            int r1 = r0 + 8;
            float4 g0 = *(const float4*)(g_gate + r0 * 4);
            float4 g1 = *(const float4*)(g_gate + r1 * 4);
            float v0 = acc[mi][ni][0] + g0.x * bs0.x + g0.y * bs0.y + g0.z * bs0.z + g0.w * bs0.w;
            float v1 = acc[mi][ni][1] + g0.x * bs1.x + g0.y * bs1.y + g0.z * bs1.z + g0.w * bs1.w;
            float v2 = acc[mi][ni][2] + g1.x * bs0.x + g1.y * bs0.y + g1.z * bs0.z + g1.w * bs0.w;
            float v3 = acc[mi][ni][3] + g1.x * bs1.x + g1.y * bs1.y + g1.z * bs1.z + g1.w * bs1.w;
            *(float2*)(out + (size_t)r0 * U_ + u0) =
                make_float2(fmaxf(v0 * cm0, 0.f), fmaxf(v1 * cm1, 0.f));
            *(float2*)(out + (size_t)r1 * U_ + u0) =
                make_float2(fmaxf(v2 * cm0, 0.f), fmaxf(v3 * cm1, 0.f));
        }
    }
}

// ---------------- launch ----------------
extern "C" void kernel_launch(void* const* d_in, const int* in_sizes, int n_in,
                              void* d_out, int out_size) {
    const float* inputs = (const float*)d_in[0];
    const float* w      = (const float*)d_in[1];
    const float* bias   = (const float*)d_in[2];
    const float* delay  = (const float*)d_in[3];
    const float* Wg     = (const float*)d_in[4];
    const float* bg     = (const float*)d_in[5];
    const float* W1     = (const float*)d_in[6];
    const float* b1     = (const float*)d_in[7];
    const float* W2     = (const float*)d_in[8];
    const float* b2     = (const float*)d_in[9];
    const float* mask   = (const float*)d_in[10];
    const float* avg    = (const float*)d_in[11];
    float* out = (float*)d_out;

    static int configured = 0;
    if (!configured) {
        cudaFuncSetAttribute(gemm_f16_kernel,
                             cudaFuncAttributeMaxDynamicSharedMemorySize, SMEM_GEMM);
        configured = 1;
    }

    hidden_kernel<<<1, 256>>>(avg, W1, b1);
    conn_kernel<<<U_ / 256, 256>>>(W2, b2, mask);
    gating_xt_kernel<<<B_, 256>>>(inputs, Wg, bg);
    wt_kernel<<<dim3(D_ / 16, U_ / 32), 256>>>(w, delay);
    gemm_f16_kernel<<<dim3(B_ / BM, U_ / BN), 256, SMEM_GEMM>>>(bias, out);
}